// round 2
// baseline (speedup 1.0000x reference)
#include <cuda_runtime.h>
#include <math.h>

// ConvLSTM T=16,B=4,Cin=32,HID=64,H=W=64, 3x3 SAME.
// Fused per-step conv(x)+conv(h)+LSTM pointwise, using packed fma.rn.f32x2.

#define T_   16
#define B_   4
#define CIN  32
#define HID  64
#define HH   64
#define WW   64
#define ICC  4
#define PROWS 34          // 32 rows + 2 halo
#define PCOLS 66          // 64 cols + 2 halo
#define PPAD  68          // padded stride (even -> 8B aligned pairs)

#define S0_FLOATS (ICC * PROWS * PPAD)              // copy 0
#define S1_FLOATS (ICC * PROWS * PPAD)              // copy shifted by 1 col
#define SW_FLOATS (ICC * 8 * 9 * 2)                 // duplicated weights
#define SMEM_BYTES ((S0_FLOATS + S1_FLOATS + SW_FLOATS) * 4)

typedef unsigned long long ull;

__device__ float g_c[B_ * HID * HH * WW];   // cell state scratch (4 MB)

__device__ __forceinline__ float sigmoidf_(float v) {
    return 1.f / (1.f + __expf(-v));
}
__device__ __forceinline__ void fma2(ull& d, ull a, ull b) {
    asm("fma.rn.f32x2 %0, %1, %2, %0;" : "+l"(d) : "l"(a), "l"(b));
}
__device__ __forceinline__ ull pk2(float lo, float hi) {
    return (ull)__float_as_uint(lo) | ((ull)__float_as_uint(hi) << 32);
}
__device__ __forceinline__ float plo(ull v) { return __uint_as_float((unsigned)v); }
__device__ __forceinline__ float phi(ull v) { return __uint_as_float((unsigned)(v >> 32)); }

__global__ __launch_bounds__(256, 2)
void convlstm_step(const float* __restrict__ x_t,     // [B, CIN, H, W]
                   const float* __restrict__ h_prev,  // [B, HID, H, W]
                   const float* __restrict__ w_x2h,   // [4*HID, CIN, 3, 3]
                   const float* __restrict__ w_h2h,   // [4*HID, HID, 3, 3]
                   const float* __restrict__ b_x2h,
                   const float* __restrict__ b_h2h,
                   float* __restrict__ h_out,         // [B, HID, H, W]
                   int first)
{
    extern __shared__ float smem[];
    float* s0 = smem;                    // [ICC][PROWS][PPAD]
    float* s1 = smem + S0_FLOATS;        // [ICC][PROWS][PPAD] (shifted -1 col)
    float* sw = smem + S0_FLOATS + S1_FLOATS;  // [ICC][8][9][2]

    const int tid = threadIdx.x;
    const int ty  = tid >> 4;            // 0..15  -> rows 2ty, 2ty+1
    const int tx  = tid & 15;            // 0..15  -> cols 4tx..4tx+3
    const int ty0 = blockIdx.x * 32;     // 2 row-tiles of 32
    const int hid_base = blockIdx.y * 2; // 2 hid channels per block
    const int b = blockIdx.z;

    // acc[l][r][p]: l = gate*2 + jh ; r row 0/1 ; p pair 0/1 (cols 4tx+2p, +1)
    ull acc[8][2][2];
#pragma unroll
    for (int l = 0; l < 8; l++) {
        int oc = (l >> 1) * HID + hid_base + (l & 1);
        float bias = b_x2h[oc] + b_h2h[oc];
        ull bb = pk2(bias, bias);
        acc[l][0][0] = bb; acc[l][0][1] = bb;
        acc[l][1][0] = bb; acc[l][1][1] = bb;
    }

    const int icTotal = first ? CIN : (CIN + HID);

    for (int ic0 = 0; ic0 < icTotal; ic0 += ICC) {
        const float* src;
        const float* wsrc;
        int wnic, ch;
        if (ic0 < CIN) {
            src = x_t + (size_t)b * CIN * HH * WW;
            wsrc = w_x2h; wnic = CIN; ch = ic0;
        } else {
            src = h_prev + (size_t)b * HID * HH * WW;
            wsrc = w_h2h; wnic = HID; ch = ic0 - CIN;
        }
        const float* base = src + (size_t)ch * HH * WW;

        // patch load (both copies), zero halo
        for (int idx = tid; idx < ICC * PROWS * PCOLS; idx += 256) {
            int ic  = idx / (PROWS * PCOLS);
            int r   = idx - ic * (PROWS * PCOLS);
            int row = r / PCOLS;
            int col = r - row * PCOLS;
            int gy = ty0 - 1 + row;
            int gx = col - 1;
            float v = 0.f;
            if ((unsigned)gy < (unsigned)HH && (unsigned)gx < (unsigned)WW)
                v = base[(size_t)ic * HH * WW + gy * WW + gx];
            s0[ic * PROWS * PPAD + row * PPAD + col] = v;
            if (col) s1[ic * PROWS * PPAD + row * PPAD + col - 1] = v;
        }
        // weights: duplicated pairs. l -> oc = (l>>1)*HID + hid_base + (l&1)
        for (int idx = tid; idx < ICC * 8 * 9; idx += 256) {
            int ic = idx / 72;
            int r  = idx - ic * 72;
            int l  = r / 9;
            int k  = r - l * 9;
            int oc = (l >> 1) * HID + hid_base + (l & 1);
            float w = wsrc[((size_t)oc * wnic + ch + ic) * 9 + k];
            sw[(idx << 1)] = w;
            sw[(idx << 1) + 1] = w;
        }
        __syncthreads();

#pragma unroll
        for (int ic = 0; ic < ICC; ic++) {
            // pairs vp[vr][j]: patch rows 2ty+vr, pair start col 4tx+j (patch coords)
            ull vp[4][5];
            const float* p0 = s0 + ic * PROWS * PPAD + (2 * ty) * PPAD + 4 * tx;
            const float* p1 = s1 + ic * PROWS * PPAD + (2 * ty) * PPAD + 4 * tx;
#pragma unroll
            for (int vr = 0; vr < 4; vr++) {
#pragma unroll
                for (int j = 0; j < 5; j++) {
                    if ((j & 1) == 0)
                        vp[vr][j] = *(const ull*)(p0 + vr * PPAD + j);
                    else
                        vp[vr][j] = *(const ull*)(p1 + vr * PPAD + (j - 1));
                }
            }
            const float* wp = sw + ic * 144;
#pragma unroll
            for (int l = 0; l < 8; l++) {
#pragma unroll
                for (int ky = 0; ky < 3; ky++) {
#pragma unroll
                    for (int kx = 0; kx < 3; kx++) {
                        ull w2 = *(const ull*)(wp + l * 18 + (ky * 3 + kx) * 2);
                        fma2(acc[l][0][0], vp[0 + ky][kx + 0], w2);
                        fma2(acc[l][0][1], vp[0 + ky][kx + 2], w2);
                        fma2(acc[l][1][0], vp[1 + ky][kx + 0], w2);
                        fma2(acc[l][1][1], vp[1 + ky][kx + 2], w2);
                    }
                }
            }
        }
        __syncthreads();
    }

    // LSTM epilogue
#pragma unroll
    for (int jh = 0; jh < 2; jh++) {
        const int hid = hid_base + jh;
#pragma unroll
        for (int r = 0; r < 2; r++) {
            const int y = ty0 + 2 * ty + r;
#pragma unroll
            for (int p = 0; p < 2; p++) {
#pragma unroll
                for (int half = 0; half < 2; half++) {
                    const int x = 4 * tx + 2 * p + half;
                    const size_t off = ((size_t)(b * HID + hid)) * HH * WW
                                     + (size_t)y * WW + x;
                    float aI = half ? phi(acc[0 * 2 + jh][r][p]) : plo(acc[0 * 2 + jh][r][p]);
                    float aF = half ? phi(acc[1 * 2 + jh][r][p]) : plo(acc[1 * 2 + jh][r][p]);
                    float aG = half ? phi(acc[2 * 2 + jh][r][p]) : plo(acc[2 * 2 + jh][r][p]);
                    float aO = half ? phi(acc[3 * 2 + jh][r][p]) : plo(acc[3 * 2 + jh][r][p]);
                    float gi = sigmoidf_(aI);
                    float gf = sigmoidf_(aF);
                    float gg = tanhf(aG);
                    float go = sigmoidf_(aO);
                    float cold = first ? 0.f : g_c[off];
                    float cn = gf * cold + gi * gg;
                    g_c[off]   = cn;
                    h_out[off] = go * tanhf(cn);
                }
            }
        }
    }
}

extern "C" void kernel_launch(void* const* d_in, const int* in_sizes, int n_in,
                              void* d_out, int out_size)
{
    const float* x     = (const float*)d_in[0];
    const float* w_x2h = (const float*)d_in[1];
    const float* b_x2h = (const float*)d_in[2];
    const float* w_h2h = (const float*)d_in[3];
    const float* b_h2h = (const float*)d_in[4];
    float* out = (float*)d_out;

    cudaFuncSetAttribute(convlstm_step,
                         cudaFuncAttributeMaxDynamicSharedMemorySize, SMEM_BYTES);

    const size_t x_step = (size_t)B_ * CIN * HH * WW;
    const size_t h_step = (size_t)B_ * HID * HH * WW;

    dim3 grid(2, HID / 2, B_);   // 2 row-tiles, 32 hid-groups, 4 batch
    for (int t = 0; t < T_; t++) {
        const float* x_t    = x + (size_t)t * x_step;
        const float* h_prev = (t == 0) ? x : out + (size_t)(t - 1) * h_step;
        float* h_out        = out + (size_t)t * h_step;
        convlstm_step<<<grid, 256, SMEM_BYTES>>>(x_t, h_prev, w_x2h, w_h2h,
                                                 b_x2h, b_h2h, h_out, t == 0 ? 1 : 0);
    }
}